// round 3
// baseline (speedup 1.0000x reference)
#include <cuda_runtime.h>

#define N_FEATS 9
#define VOCAB   119
#define HIDDEN  128
#define MAXN    50176   // capacity for scratch (N = 50000 in this problem)

// Scratch for q/k/v between the two kernels (no allocations allowed).
__device__ float g_q[MAXN * HIDDEN];
__device__ float g_k[MAXN * HIDDEN];
__device__ float g_v[MAXN * HIDDEN];

// 1 if nbr_mask buffer is int32-encoded bools, 0 if uint8-encoded.
__device__ int g_mask_i32;

// ---------------------------------------------------------------------------
// Kernel 0: detect mask dtype. For int32-encoded 0/1 bools (little-endian),
// bytes at offsets 1..3 of every 4-byte group are zero. For genuine uint8
// random bools the chance all 1024 groups look like that is (1/8)^1024 ~ 0.
// ---------------------------------------------------------------------------
__global__ void k_detect_mask(const unsigned char* __restrict__ mask)
{
    if (blockIdx.x == 0 && threadIdx.x == 0) {
        int i32 = 1;
        for (int g = 0; g < 1024; g++) {
            if (mask[g * 4 + 1] | mask[g * 4 + 2] | mask[g * 4 + 3]) { i32 = 0; break; }
        }
        g_mask_i32 = i32;
    }
}

// ---------------------------------------------------------------------------
// Kernel 1: AtomEncoder (sum of 9 embedding lookups) + fused Q/K/V projections.
// 64 nodes per CTA, 256 threads. Thread owns column c = tid&127 and node-half
// ng = tid>>7 (32 nodes). h tile staged in smem; inner product j-blocked by 4
// with a single broadcast LDS.128 per (node, j4) -> FMA:LDS = 4:1.
// ---------------------------------------------------------------------------
__device__ __forceinline__ void gemm_tile(
    const float* __restrict__ sh_h,        // [64][HIDDEN]
    const float* __restrict__ W,           // [HIDDEN][HIDDEN] row-major
    const float* __restrict__ bias,        // [HIDDEN]
    float* __restrict__ out,               // [N][HIDDEN]
    float scale, int node0, int N, int c, int ng)
{
    float acc[32];
#pragma unroll
    for (int i = 0; i < 32; i++) acc[i] = 0.f;

#pragma unroll 4
    for (int j4 = 0; j4 < 32; j4++) {
        const float w0 = W[(j4 * 4 + 0) * HIDDEN + c];
        const float w1 = W[(j4 * 4 + 1) * HIDDEN + c];
        const float w2 = W[(j4 * 4 + 2) * HIDDEN + c];
        const float w3 = W[(j4 * 4 + 3) * HIDDEN + c];
#pragma unroll
        for (int nn = 0; nn < 32; nn++) {
            const float4 h4 = *reinterpret_cast<const float4*>(
                &sh_h[(ng * 32 + nn) * HIDDEN + j4 * 4]);
            float a = acc[nn];
            a = fmaf(h4.x, w0, a);
            a = fmaf(h4.y, w1, a);
            a = fmaf(h4.z, w2, a);
            a = fmaf(h4.w, w3, a);
            acc[nn] = a;
        }
    }

    const float b = bias[c];
#pragma unroll
    for (int nn = 0; nn < 32; nn++) {
        const int node = node0 + ng * 32 + nn;
        if (node < N) out[node * HIDDEN + c] = (acc[nn] + b) * scale;
    }
}

__global__ __launch_bounds__(256) void k_encode_qkv(
    const int*   __restrict__ X,       // [N][9]
    const float* __restrict__ emb,     // [9][119][128]
    const float* __restrict__ Wq, const float* __restrict__ bq,
    const float* __restrict__ Wk, const float* __restrict__ bk,
    const float* __restrict__ Wv, const float* __restrict__ bv,
    int N)
{
    __shared__ float sh_h[64 * HIDDEN];   // 32 KB
    __shared__ int   sh_x[64 * N_FEATS];

    const int tid   = threadIdx.x;
    const int node0 = blockIdx.x * 64;

    // Stage X rows (clamped for the tail block; stores are guarded later).
    for (int i = tid; i < 64 * N_FEATS; i += 256) {
        const int node = min(node0 + i / N_FEATS, N - 1);
        sh_x[i] = X[node * N_FEATS + (i % N_FEATS)];
    }
    __syncthreads();

    // h[node][c] = sum_f emb[f][X[node][f]][c]; coalesced over c.
    for (int i = tid; i < 64 * HIDDEN; i += 256) {
        const int node = i >> 7;
        const int c    = i & 127;
        float s = 0.f;
#pragma unroll
        for (int f = 0; f < N_FEATS; f++) {
            const int x = sh_x[node * N_FEATS + f];
            s += emb[(f * VOCAB + x) * HIDDEN + c];
        }
        sh_h[i] = s;
    }
    __syncthreads();

    const int c  = tid & 127;
    const int ng = tid >> 7;
    gemm_tile(sh_h, Wq, bq, g_q, 0.25f, node0, N, c, ng);  // scaling = 16^-0.5
    gemm_tile(sh_h, Wk, bk, g_k, 1.0f,  node0, N, c, ng);
    gemm_tile(sh_h, Wv, bv, g_v, 1.0f,  node0, N, c, ng);
}

// ---------------------------------------------------------------------------
// Kernel 2: ELL sparse attention. One warp per node. Lane l owns dims
// [4l, 4l+4) -> head = l>>2; head-dot reduced with 2x shfl_xor inside the
// 4-lane group. V rows held in 64 registers to avoid a second gather pass.
// ---------------------------------------------------------------------------
__global__ __launch_bounds__(256, 2) void k_attn(
    const int*           __restrict__ nbr_idx,   // [N][16]
    const unsigned char* __restrict__ nbr_mask,  // [N][16] bools (u8 or i32)
    float*               __restrict__ out,       // [N][128]
    int N)
{
    const int warp = (blockIdx.x * blockDim.x + threadIdx.x) >> 5;
    const int lane = threadIdx.x & 31;
    if (warp >= N) return;
    const int n = warp;

    const int mask_i32 = g_mask_i32;

    int      jreg = 0;
    unsigned mreg = 0;
    if (lane < 16) {
        jreg = nbr_idx[n * 16 + lane];
        mreg = mask_i32
             ? (unsigned)reinterpret_cast<const int*>(nbr_mask)[n * 16 + lane]
             : (unsigned)nbr_mask[n * 16 + lane];
    }

    const float4 q4 = reinterpret_cast<const float4*>(g_q)[n * 32 + lane];

    float  sc[16];
    float4 vb[16];
#pragma unroll
    for (int kk = 0; kk < 16; kk++) {
        const int      j = __shfl_sync(0xffffffffu, jreg, kk);
        const unsigned m = __shfl_sync(0xffffffffu, mreg, kk);
        const float4  kv = reinterpret_cast<const float4*>(g_k)[j * 32 + lane];
        vb[kk]           = reinterpret_cast<const float4*>(g_v)[j * 32 + lane];
        float d = q4.x * kv.x + q4.y * kv.y + q4.z * kv.z + q4.w * kv.w;
        d += __shfl_xor_sync(0xffffffffu, d, 1);
        d += __shfl_xor_sync(0xffffffffu, d, 2);   // full 16-dim head dot
        sc[kk] = m ? d : -1e9f;
    }

    // Softmax over the 16 neighbors (per head; replicated across the 4 lanes).
    float mx = -1e30f;
#pragma unroll
    for (int kk = 0; kk < 16; kk++) mx = fmaxf(mx, sc[kk]);
    float s = 0.f;
#pragma unroll
    for (int kk = 0; kk < 16; kk++) { sc[kk] = __expf(sc[kk] - mx); s += sc[kk]; }
    const float inv = 1.f / s;

    float4 acc = make_float4(0.f, 0.f, 0.f, 0.f);
#pragma unroll
    for (int kk = 0; kk < 16; kk++) {
        const float p = sc[kk] * inv;
        acc.x = fmaf(p, vb[kk].x, acc.x);
        acc.y = fmaf(p, vb[kk].y, acc.y);
        acc.z = fmaf(p, vb[kk].z, acc.z);
        acc.w = fmaf(p, vb[kk].w, acc.w);
    }
    reinterpret_cast<float4*>(out)[n * 32 + lane] = acc;
}

// ---------------------------------------------------------------------------
// Launch
// ---------------------------------------------------------------------------
extern "C" void kernel_launch(void* const* d_in, const int* in_sizes, int n_in,
                              void* d_out, int out_size)
{
    const int*           X        = (const int*)d_in[0];
    const int*           nbr_idx  = (const int*)d_in[1];
    const unsigned char* nbr_mask = (const unsigned char*)d_in[2];
    const float*         emb      = (const float*)d_in[3];
    const float*         Wq       = (const float*)d_in[4];
    const float*         bq       = (const float*)d_in[5];
    const float*         Wk       = (const float*)d_in[6];
    const float*         bk       = (const float*)d_in[7];
    const float*         Wv       = (const float*)d_in[8];
    const float*         bv       = (const float*)d_in[9];
    float*               out      = (float*)d_out;

    const int N = in_sizes[0] / N_FEATS;

    k_detect_mask<<<1, 32>>>(nbr_mask);

    const int grid1 = (N + 63) / 64;
    k_encode_qkv<<<grid1, 256>>>(X, emb, Wq, bq, Wk, bk, Wv, bv, N);

    const int grid2 = (N + 7) / 8;   // 8 warps per 256-thread block
    k_attn<<<grid2, 256>>>(nbr_idx, nbr_mask, out, N);
}

// round 4
// speedup vs baseline: 1.1955x; 1.1955x over previous
#include <cuda_runtime.h>

#define N_FEATS 9
#define VOCAB   119
#define HIDDEN  128
#define MAXN    50176     // capacity for scratch (N = 50000 in this problem)
#define SH_STR  68        // padded stride for transposed h tile (16B-aligned rows)

// Scratch for q/k/v between the two kernels (no allocations allowed).
__device__ float g_q[MAXN * HIDDEN];
__device__ float g_k[MAXN * HIDDEN];
__device__ float g_v[MAXN * HIDDEN];

// 1 if nbr_mask buffer is int32-encoded bools, 0 if uint8-encoded.
__device__ int g_mask_i32;

// ---------------------------------------------------------------------------
// f32x2 packed-FMA helpers (FFMA2: 2 MACs per lane-instruction on sm_103a).
// ---------------------------------------------------------------------------
__device__ __forceinline__ unsigned long long pack2(float x, float y) {
    unsigned long long r;
    asm("mov.b64 %0, {%1, %2};" : "=l"(r) : "f"(x), "f"(y));
    return r;
}
__device__ __forceinline__ void unpack2(unsigned long long d, float& x, float& y) {
    asm("mov.b64 {%0, %1}, %2;" : "=f"(x), "=f"(y) : "l"(d));
}
__device__ __forceinline__ void ffma2(unsigned long long& d,
                                      unsigned long long a, unsigned long long b) {
    asm("fma.rn.f32x2 %0, %1, %2, %0;" : "+l"(d) : "l"(a), "l"(b));
}

// ---------------------------------------------------------------------------
// Kernel 0: detect mask dtype (parallel). int32-encoded bools have bytes 1..3
// of every 4-byte group zero; chance of that for 1024 random u8 bool groups
// is (1/8)^1024 ~ 0.
// ---------------------------------------------------------------------------
__global__ void k_detect_mask(const unsigned char* __restrict__ mask)
{
    const int t = threadIdx.x;
    int ok = 1;
    for (int g = t; g < 1024; g += 256)
        if (mask[g * 4 + 1] | mask[g * 4 + 2] | mask[g * 4 + 3]) ok = 0;
    ok = __syncthreads_and(ok);
    if (t == 0) g_mask_i32 = ok;
}

// ---------------------------------------------------------------------------
// Kernel 1: AtomEncoder + fused Q/K/V projections with packed FFMA2.
// 64 nodes/CTA, 256 threads. h tile stored TRANSPOSED: sh_ht[j][node].
// Thread owns column c = tid&127 and node-half ng = tid>>7 (32 nodes as 16
// packed pairs). Per j: broadcast LDS.128 gives 2 packed node-pairs; weight
// (w,w) packed once; 16 FFMA2 per j per thread.
// ---------------------------------------------------------------------------
__device__ __forceinline__ void gemm_tile(
    const float* __restrict__ sh_ht,       // [HIDDEN][SH_STR] transposed h
    const float* __restrict__ W,           // [HIDDEN][HIDDEN] row-major
    const float* __restrict__ bias,        // [HIDDEN]
    float* __restrict__ out,               // [N][HIDDEN]
    float scale, int node0, int N, int c, int ng)
{
    unsigned long long acc[16];
#pragma unroll
    for (int i = 0; i < 16; i++) acc[i] = 0ull;

#pragma unroll 4
    for (int j = 0; j < HIDDEN; j++) {
        const float w = __ldg(&W[j * HIDDEN + c]);
        const unsigned long long ww = pack2(w, w);
        const float* hrow = &sh_ht[j * SH_STR + ng * 32];
#pragma unroll
        for (int p4 = 0; p4 < 8; p4++) {
            const ulonglong2 hh =
                *reinterpret_cast<const ulonglong2*>(&hrow[p4 * 4]);
            ffma2(acc[2 * p4 + 0], hh.x, ww);
            ffma2(acc[2 * p4 + 1], hh.y, ww);
        }
    }

    const float b = bias[c];
#pragma unroll
    for (int p = 0; p < 16; p++) {
        float x, y;
        unpack2(acc[p], x, y);
        const int node = node0 + ng * 32 + 2 * p;
        if (node < N)     out[node * HIDDEN + c]       = (x + b) * scale;
        if (node + 1 < N) out[(node + 1) * HIDDEN + c] = (y + b) * scale;
    }
}

__global__ __launch_bounds__(256) void k_encode_qkv(
    const int*   __restrict__ X,       // [N][9]
    const float* __restrict__ emb,     // [9][119][128]
    const float* __restrict__ Wq, const float* __restrict__ bq,
    const float* __restrict__ Wk, const float* __restrict__ bk,
    const float* __restrict__ Wv, const float* __restrict__ bv,
    int N)
{
    __shared__ __align__(16) float sh_ht[HIDDEN * SH_STR];  // 34.8 KB transposed
    __shared__ int sh_x[64 * N_FEATS];

    const int tid   = threadIdx.x;
    const int node0 = blockIdx.x * 64;

    // Stage X rows (clamped for the tail block; stores are guarded later).
    for (int i = tid; i < 64 * N_FEATS; i += 256) {
        const int node = min(node0 + i / N_FEATS, N - 1);
        sh_x[i] = X[node * N_FEATS + (i % N_FEATS)];
    }
    __syncthreads();

    // h[node][c] = sum_f emb[f][X[node][f]][c]; coalesced over c in gmem,
    // stored transposed: sh_ht[c][node].
    for (int i = tid; i < 64 * HIDDEN; i += 256) {
        const int node = i >> 7;
        const int c    = i & 127;
        float s = 0.f;
#pragma unroll
        for (int f = 0; f < N_FEATS; f++) {
            const int x = sh_x[node * N_FEATS + f];
            s += emb[(f * VOCAB + x) * HIDDEN + c];
        }
        sh_ht[c * SH_STR + node] = s;
    }
    __syncthreads();

    const int c  = tid & 127;
    const int ng = tid >> 7;
    gemm_tile(sh_ht, Wq, bq, g_q, 0.25f, node0, N, c, ng);  // scaling = 16^-0.5
    gemm_tile(sh_ht, Wk, bk, g_k, 1.0f,  node0, N, c, ng);
    gemm_tile(sh_ht, Wv, bv, g_v, 1.0f,  node0, N, c, ng);
}

// ---------------------------------------------------------------------------
// Kernel 2: ELL sparse attention. One warp per node. Lane l owns dims
// [4l, 4l+4) -> head = l>>2; head-dot reduced with 2x shfl_xor inside the
// 4-lane group. V rows held in 64 registers to avoid a second gather pass.
// ---------------------------------------------------------------------------
__global__ __launch_bounds__(256, 2) void k_attn(
    const int*           __restrict__ nbr_idx,   // [N][16]
    const unsigned char* __restrict__ nbr_mask,  // [N][16] bools (u8 or i32)
    float*               __restrict__ out,       // [N][128]
    int N)
{
    const int warp = (blockIdx.x * blockDim.x + threadIdx.x) >> 5;
    const int lane = threadIdx.x & 31;
    if (warp >= N) return;
    const int n = warp;

    const int mask_i32 = g_mask_i32;

    int      jreg = 0;
    unsigned mreg = 0;
    if (lane < 16) {
        jreg = nbr_idx[n * 16 + lane];
        mreg = mask_i32
             ? (unsigned)reinterpret_cast<const int*>(nbr_mask)[n * 16 + lane]
             : (unsigned)nbr_mask[n * 16 + lane];
    }

    const float4 q4 = reinterpret_cast<const float4*>(g_q)[n * 32 + lane];

    float  sc[16];
    float4 vb[16];
#pragma unroll
    for (int kk = 0; kk < 16; kk++) {
        const int      j = __shfl_sync(0xffffffffu, jreg, kk);
        const unsigned m = __shfl_sync(0xffffffffu, mreg, kk);
        const float4  kv = reinterpret_cast<const float4*>(g_k)[j * 32 + lane];
        vb[kk]           = reinterpret_cast<const float4*>(g_v)[j * 32 + lane];
        float d = q4.x * kv.x + q4.y * kv.y + q4.z * kv.z + q4.w * kv.w;
        d += __shfl_xor_sync(0xffffffffu, d, 1);
        d += __shfl_xor_sync(0xffffffffu, d, 2);   // full 16-dim head dot
        sc[kk] = m ? d : -1e9f;
    }

    // Softmax over the 16 neighbors (per head; replicated across the 4 lanes).
    float mx = -1e30f;
#pragma unroll
    for (int kk = 0; kk < 16; kk++) mx = fmaxf(mx, sc[kk]);
    float s = 0.f;
#pragma unroll
    for (int kk = 0; kk < 16; kk++) { sc[kk] = __expf(sc[kk] - mx); s += sc[kk]; }
    const float inv = 1.f / s;

    float4 acc = make_float4(0.f, 0.f, 0.f, 0.f);
#pragma unroll
    for (int kk = 0; kk < 16; kk++) {
        const float p = sc[kk] * inv;
        acc.x = fmaf(p, vb[kk].x, acc.x);
        acc.y = fmaf(p, vb[kk].y, acc.y);
        acc.z = fmaf(p, vb[kk].z, acc.z);
        acc.w = fmaf(p, vb[kk].w, acc.w);
    }
    reinterpret_cast<float4*>(out)[n * 32 + lane] = acc;
}

// ---------------------------------------------------------------------------
// Launch
// ---------------------------------------------------------------------------
extern "C" void kernel_launch(void* const* d_in, const int* in_sizes, int n_in,
                              void* d_out, int out_size)
{
    const int*           X        = (const int*)d_in[0];
    const int*           nbr_idx  = (const int*)d_in[1];
    const unsigned char* nbr_mask = (const unsigned char*)d_in[2];
    const float*         emb      = (const float*)d_in[3];
    const float*         Wq       = (const float*)d_in[4];
    const float*         bq       = (const float*)d_in[5];
    const float*         Wk       = (const float*)d_in[6];
    const float*         bk       = (const float*)d_in[7];
    const float*         Wv       = (const float*)d_in[8];
    const float*         bv       = (const float*)d_in[9];
    float*               out      = (float*)d_out;

    const int N = in_sizes[0] / N_FEATS;

    k_detect_mask<<<1, 256>>>(nbr_mask);

    const int grid1 = (N + 63) / 64;
    k_encode_qkv<<<grid1, 256>>>(X, emb, Wq, bq, Wk, bk, Wv, bv, N);

    const int grid2 = (N + 7) / 8;   // 8 warps per 256-thread block
    k_attn<<<grid2, 256>>>(nbr_idx, nbr_mask, out, N);
}